// round 2
// baseline (speedup 1.0000x reference)
#include <cuda_runtime.h>
#include <math.h>

#define T_STEPS 200
#define NB      256         // batch (NUM_PROP)
#define H       512
#define C_IN    128
#define G4      2048        // 4*H

// ---------------- scratch (device globals; no allocations allowed) ----------
__device__ float g_xp[(size_t)T_STEPS * NB * G4];   // xproj for current layer (reused)
__device__ float g_h0[(size_t)T_STEPS * NB * H];    // layer-0 hidden history
__device__ float g_h1[(size_t)T_STEPS * NB * H];    // layer-1 hidden history
__device__ float g_c0[NB * H];
__device__ float g_c1[NB * H];
__device__ float g_hz[NB * H];                      // stays zero (never written)

// ---------------- zero init: d_out + cell states ----------------------------
__global__ void zero_kernel(float* __restrict__ out, int out_size) {
    int i = blockIdx.x * blockDim.x + threadIdx.x;
    int stride = gridDim.x * blockDim.x;
    for (int k = i; k < out_size; k += stride) out[k] = 0.f;
    for (int k = i; k < NB * H; k += stride) { g_c0[k] = 0.f; g_c1[k] = 0.f; }
}

// ---------------- xproj GEMM: out[m][n] = sum_k A[m][k]*W[n][k] + bih[n]+bhh[n]
// m = t*256 + b ; A element addressed as A[b*sB + t*sT + k]
// M = 51200, N = 2048.  Block tile 64x64, BK=16, 256 threads, 4x4 microtile.
__global__ void xproj_gemm(const float* __restrict__ Aext,
                           const float* __restrict__ W,
                           const float* __restrict__ bih,
                           const float* __restrict__ bhh,
                           int K, int sB, int sT, int useH0)
{
    __shared__ float As[16][68];
    __shared__ float Bs[16][68];

    const float* A = useH0 ? g_h0 : Aext;
    const int n0 = blockIdx.x * 64;
    const int m0 = blockIdx.y * 64;
    const int tid = threadIdx.x;          // 256
    const int tx = tid & 15, ty = tid >> 4;

    float acc[4][4] = {};

    for (int k0 = 0; k0 < K; k0 += 16) {
        #pragma unroll
        for (int i = 0; i < 4; i++) {
            int e = tid + i * 256;
            int mm = e >> 4, kk = e & 15;
            int m = m0 + mm;
            int b = m & 255, t = m >> 8;
            As[kk][mm] = A[(size_t)b * sB + (size_t)t * sT + k0 + kk];
        }
        #pragma unroll
        for (int i = 0; i < 4; i++) {
            int e = tid + i * 256;
            int nn = e >> 4, kk = e & 15;
            Bs[kk][nn] = W[(size_t)(n0 + nn) * K + k0 + kk];
        }
        __syncthreads();
        #pragma unroll
        for (int kk = 0; kk < 16; kk++) {
            float4 av = *(const float4*)&As[kk][ty * 4];
            float4 bv = *(const float4*)&Bs[kk][tx * 4];
            float a[4] = {av.x, av.y, av.z, av.w};
            float bb[4] = {bv.x, bv.y, bv.z, bv.w};
            #pragma unroll
            for (int r = 0; r < 4; r++)
                #pragma unroll
                for (int c = 0; c < 4; c++)
                    acc[r][c] += a[r] * bb[c];
        }
        __syncthreads();
    }

    #pragma unroll
    for (int r = 0; r < 4; r++) {
        int m = m0 + ty * 4 + r;
        float4 v;
        float* vp = (float*)&v;
        #pragma unroll
        for (int c = 0; c < 4; c++) {
            int n = n0 + tx * 4 + c;
            vp[c] = acc[r][c] + bih[n] + bhh[n];
        }
        *(float4*)&g_xp[(size_t)m * G4 + n0 + tx * 4] = v;
    }
}

// ---------------- fused LSTM step: gates = xp[t] + h_prev @ Whh^T, cell update
// Block tile: 32 batch x 128 gate-cols (= 4 gates x 32 j), K=512.
// grid = (16 j-tiles, 8 b-tiles), 256 threads, 4x4 microtile.
__global__ void lstm_step(const float* __restrict__ Whh, int t, int layer)
{
    __shared__ float As[32][36];
    __shared__ float Bs[32][132];   // reused as gate staging after GEMM

    float* hbase = layer ? g_h1 : g_h0;
    const float* hp = (t == 0) ? g_hz : hbase + (size_t)(t - 1) * NB * H;
    float* hout = hbase + (size_t)t * NB * H;
    float* cst = layer ? g_c1 : g_c0;
    const float* xp = g_xp + (size_t)t * NB * G4;

    const int j0 = blockIdx.x * 32;
    const int b0 = blockIdx.y * 32;
    const int tid = threadIdx.x;
    const int tx = tid & 31, ty = tid >> 5;

    float acc[4][4] = {};

    for (int k0 = 0; k0 < H; k0 += 32) {
        #pragma unroll
        for (int i = 0; i < 4; i++) {
            int e = tid + i * 256;
            int bb = e >> 5, kk = e & 31;
            As[kk][bb] = hp[(size_t)(b0 + bb) * H + k0 + kk];
        }
        #pragma unroll
        for (int i = 0; i < 16; i++) {
            int e = tid + i * 256;
            int nn = e >> 5, kk = e & 31;
            int gate = nn >> 5, jj = nn & 31;
            Bs[kk][nn] = Whh[(size_t)(gate * H + j0 + jj) * H + k0 + kk];
        }
        __syncthreads();
        #pragma unroll
        for (int kk = 0; kk < 32; kk++) {
            float4 av = *(const float4*)&As[kk][ty * 4];
            float4 bv = *(const float4*)&Bs[kk][tx * 4];
            float a[4] = {av.x, av.y, av.z, av.w};
            float bb[4] = {bv.x, bv.y, bv.z, bv.w};
            #pragma unroll
            for (int r = 0; r < 4; r++)
                #pragma unroll
                for (int c = 0; c < 4; c++)
                    acc[r][c] += a[r] * bb[c];
        }
        __syncthreads();
    }

    // stage gates (+xproj) to smem (reuse Bs)
    float* gs = &Bs[0][0];
    #pragma unroll
    for (int r = 0; r < 4; r++) {
        int bb = ty * 4 + r;
        int bglob = b0 + bb;
        #pragma unroll
        for (int c = 0; c < 4; c++) {
            int nn = tx * 4 + c;
            int gate = nn >> 5, jj = nn & 31;
            gs[bb * 132 + nn] = acc[r][c] + xp[(size_t)bglob * G4 + gate * H + j0 + jj];
        }
    }
    __syncthreads();

    // cell + hidden update: 1024 (b,j) pairs, 4 per thread
    #pragma unroll
    for (int i = 0; i < 4; i++) {
        int p = tid + i * 256;
        int bb = p >> 5, jj = p & 31;
        float gi = gs[bb * 132 + jj];
        float gf = gs[bb * 132 + 32 + jj];
        float gg = gs[bb * 132 + 64 + jj];
        float go = gs[bb * 132 + 96 + jj];
        float iv = 1.f / (1.f + expf(-gi));
        float fv = 1.f / (1.f + expf(-gf));
        float gv = tanhf(gg);
        float ov = 1.f / (1.f + expf(-go));
        size_t idx = (size_t)(b0 + bb) * H + j0 + jj;
        float cn = fv * cst[idx] + iv * gv;
        cst[idx] = cn;
        hout[idx] = ov * tanhf(cn);
    }
}

// ---------------- heads: cls [256,40], bbox [256,2] from h1[:,199,:] --------
__global__ void heads_kernel(const float* __restrict__ cls_W,
                             const float* __restrict__ cls_b,
                             const float* __restrict__ bbox_W,
                             const float* __restrict__ bbox_b,
                             float* __restrict__ out)
{
    __shared__ float base[H];
    int b = blockIdx.x;
    const float* src = g_h1 + (size_t)(T_STEPS - 1) * NB * H + (size_t)b * H;
    for (int k = threadIdx.x; k < H; k += blockDim.x) base[k] = src[k];
    __syncthreads();
    for (int o = threadIdx.x; o < 42; o += blockDim.x) {
        const float* w = (o < 40) ? &cls_W[o * H] : &bbox_W[(o - 40) * H];
        float s = (o < 40) ? cls_b[o] : bbox_b[o - 40];
        #pragma unroll 8
        for (int k = 0; k < H; k++) s += base[k] * w[k];
        if (o < 40) out[b * 40 + o] = s;
        else        out[NB * 40 + b * 2 + (o - 40)] = s;
    }
    // cls_loss / bbox_loss scalars stay 0 from zero_kernel
}

extern "C" void kernel_launch(void* const* d_in, const int* in_sizes, int n_in,
                              void* d_out, int out_size)
{
    const float* proposals = (const float*)d_in[2];
    const float* Wih0   = (const float*)d_in[4];
    const float* Whh0   = (const float*)d_in[5];
    const float* bih0   = (const float*)d_in[6];
    const float* bhh0   = (const float*)d_in[7];
    const float* Wih1   = (const float*)d_in[8];
    const float* Whh1   = (const float*)d_in[9];
    const float* bih1   = (const float*)d_in[10];
    const float* bhh1   = (const float*)d_in[11];
    const float* cls_W  = (const float*)d_in[12];
    const float* cls_b  = (const float*)d_in[13];
    const float* bbox_W = (const float*)d_in[14];
    const float* bbox_b = (const float*)d_in[15];
    float* out = (float*)d_out;

    zero_kernel<<<256, 256>>>(out, out_size);

    dim3 gx(G4 / 64, (T_STEPS * NB) / 64);   // (32, 800)
    dim3 gstep(16, 8);

    // layer 0
    xproj_gemm<<<gx, 256>>>(proposals, Wih0, bih0, bhh0, C_IN, T_STEPS * C_IN, C_IN, 0);
    for (int t = 0; t < T_STEPS; t++)
        lstm_step<<<gstep, 256>>>(Whh0, t, 0);

    // layer 1 (xproj from g_h0, reuses g_xp)
    xproj_gemm<<<gx, 256>>>(proposals, Wih1, bih1, bhh1, H, H, NB * H, 1);
    for (int t = 0; t < T_STEPS; t++)
        lstm_step<<<gstep, 256>>>(Whh1, t, 1);

    heads_kernel<<<NB, 64>>>(cls_W, cls_b, bbox_W, bbox_b, out);
}

// round 6
// speedup vs baseline: 1.7044x; 1.7044x over previous
#include <cuda_runtime.h>
#include <cuda_bf16.h>
#include <cstdint>
#include <math.h>

#define T_STEPS 200
#define NB      256
#define H       512
#define CIN     128
#define G4      2048

#define BM 64
#define BN 64
#define BK 32
#define LDT 40      // smem tile row stride in bf16 elems (80B, conflict-free for ldmatrix)
#define GST 72      // gate-staging row stride in floats

// ---------------- device scratch ----------------
__device__ __nv_bfloat16 g_wih_hi0[G4*CIN], g_wih_lo0[G4*CIN];
__device__ __nv_bfloat16 g_wih_hi1[G4*H],   g_wih_lo1[G4*H];
__device__ __nv_bfloat16 g_whh_hi0[G4*H],   g_whh_lo0[G4*H];
__device__ __nv_bfloat16 g_whh_hi1[G4*H],   g_whh_lo1[G4*H];
__device__ __nv_bfloat16 g_h_hi0[(size_t)T_STEPS*NB*H], g_h_lo0[(size_t)T_STEPS*NB*H];
__device__ __nv_bfloat16 g_h_hi1[(size_t)T_STEPS*NB*H], g_h_lo1[(size_t)T_STEPS*NB*H];
__device__ __nv_bfloat16 g_x_hi[(size_t)T_STEPS*NB*CIN], g_x_lo[(size_t)T_STEPS*NB*CIN];
__device__ __nv_bfloat16 g_hz_hi[NB*H], g_hz_lo[NB*H];     // stays zero
__device__ float g_xp[(size_t)T_STEPS*NB*G4];
__device__ float g_c0[NB*H], g_c1[NB*H];
__device__ float g_base[NB*H];

// ---------------- helpers ----------------
__device__ __forceinline__ uint32_t smem_u32(const void* p) {
    return (uint32_t)__cvta_generic_to_shared(p);
}
__device__ __forceinline__ void ldm_x4(uint32_t& r0, uint32_t& r1, uint32_t& r2, uint32_t& r3,
                                       uint32_t addr) {
    asm volatile("ldmatrix.sync.aligned.m8n8.x4.shared.b16 {%0,%1,%2,%3}, [%4];"
                 : "=r"(r0), "=r"(r1), "=r"(r2), "=r"(r3) : "r"(addr));
}
__device__ __forceinline__ void mma_bf16(float* c, const uint32_t* a, uint32_t b0, uint32_t b1) {
    asm volatile("mma.sync.aligned.m16n8k16.row.col.f32.bf16.bf16.f32 "
                 "{%0,%1,%2,%3}, {%4,%5,%6,%7}, {%8,%9}, {%0,%1,%2,%3};"
                 : "+f"(c[0]), "+f"(c[1]), "+f"(c[2]), "+f"(c[3])
                 : "r"(a[0]), "r"(a[1]), "r"(a[2]), "r"(a[3]), "r"(b0), "r"(b1));
}
__device__ __forceinline__ float sigf(float x) { return 1.f / (1.f + expf(-x)); }

// ---------------- init ----------------
__global__ void zero_kernel(float* __restrict__ out, int out_size) {
    int i = blockIdx.x * blockDim.x + threadIdx.x;
    int s = gridDim.x * blockDim.x;
    for (int k = i; k < out_size; k += s) out[k] = 0.f;
    for (int k = i; k < NB * H; k += s) { g_c0[k] = 0.f; g_c1[k] = 0.f; }
}

// ---------------- fp32 -> bf16 hi/lo ----------------
__global__ void conv_w(const float* __restrict__ src, int which, int n) {
    int i = blockIdx.x * blockDim.x + threadIdx.x;
    if (i >= n) return;
    float v = src[i];
    __nv_bfloat16 h = __float2bfloat16(v);
    __nv_bfloat16 l = __float2bfloat16(v - __bfloat162float(h));
    switch (which) {
        case 0: g_wih_hi0[i] = h; g_wih_lo0[i] = l; break;
        case 1: g_whh_hi0[i] = h; g_whh_lo0[i] = l; break;
        case 2: g_wih_hi1[i] = h; g_wih_lo1[i] = l; break;
        case 3: g_whh_hi1[i] = h; g_whh_lo1[i] = l; break;
    }
}
// proposals [b, t, c] -> g_x rows m = t*256+b
__global__ void conv_x(const float* __restrict__ prop) {
    int i = blockIdx.x * blockDim.x + threadIdx.x;
    if (i >= T_STEPS * NB * CIN) return;
    int k = i & (CIN - 1);
    int m = i >> 7;
    int b = m & (NB - 1), t = m >> 8;
    float v = prop[((size_t)b * T_STEPS + t) * CIN + k];
    __nv_bfloat16 h = __float2bfloat16(v);
    g_x_hi[i] = h;
    g_x_lo[i] = __float2bfloat16(v - __bfloat162float(h));
}

// ---------------- shared GEMM core (mma.sync bf16-split, 3 products) --------
// IS_STEP=false: g_xp[m0.., n0..] = A[51200 x K] * W^T + bias
// IS_STEP=true : fused LSTM step; CTA tile = 64 batch x (4 gates x 16 j)
template<bool IS_STEP>
__global__ void __launch_bounds__(256) gemm_mma(int K, int t, int layer,
                                                const float* __restrict__ bih,
                                                const float* __restrict__ bhh) {
    __shared__ __align__(16) __nv_bfloat16 Ah[BM][LDT], Al[BM][LDT];
    __shared__ __align__(16) __nv_bfloat16 Bh[BM][LDT], Bl[BM][LDT];
    __shared__ float sbias[BN];

    const int tid  = threadIdx.x;
    const int lane = tid & 31;
    const int warp = tid >> 5;
    const int wm = warp >> 2;           // 0..1 -> 32 rows each
    const int wn = warp & 3;            // 0..3 -> 16 cols each

    const __nv_bfloat16 *Aptr_hi, *Aptr_lo, *Bptr_hi, *Bptr_lo;
    const int m0 = blockIdx.y * BM;
    int j0 = 0, n0 = 0;

    if constexpr (IS_STEP) {
        j0 = blockIdx.x * 16;
        const __nv_bfloat16* hb_hi = layer ? g_h_hi1 : g_h_hi0;
        const __nv_bfloat16* hb_lo = layer ? g_h_lo1 : g_h_lo0;
        Aptr_hi = (t == 0) ? g_hz_hi : hb_hi + (size_t)(t - 1) * NB * H;
        Aptr_lo = (t == 0) ? g_hz_lo : hb_lo + (size_t)(t - 1) * NB * H;
        Bptr_hi = layer ? g_whh_hi1 : g_whh_hi0;
        Bptr_lo = layer ? g_whh_lo1 : g_whh_lo0;
    } else {
        n0 = blockIdx.x * BN;
        Aptr_hi = layer ? g_h_hi0 : g_x_hi;
        Aptr_lo = layer ? g_h_lo0 : g_x_lo;
        Bptr_hi = layer ? g_wih_hi1 : g_wih_hi0;
        Bptr_lo = layer ? g_wih_lo1 : g_wih_lo0;
        if (tid < BN) sbias[tid] = bih[n0 + tid] + bhh[n0 + tid];
    }

    float acc[2][2][4] = {};

    const int lrow = tid >> 2;          // 0..63
    const int lseg = (tid & 3) * 8;     // 0,8,16,24
    int browg;
    if constexpr (IS_STEP) browg = (lrow >> 4) * H + j0 + (lrow & 15);
    else                   browg = n0 + lrow;

    // frag smem addresses (constant across k-loop except kk offset)
    const uint32_t aAddrBase[2] = {
        smem_u32(&Ah[wm * 32 + (lane & 15)][(lane >> 4) * 8]),
        smem_u32(&Al[wm * 32 + (lane & 15)][(lane >> 4) * 8])
    };
    const uint32_t bAddrBase[2] = {
        smem_u32(&Bh[wn * 16 + ((lane >> 4) << 3) + (lane & 7)][((lane >> 3) & 1) * 8]),
        smem_u32(&Bl[wn * 16 + ((lane >> 4) << 3) + (lane & 7)][((lane >> 3) & 1) * 8])
    };

    for (int c0 = 0; c0 < K; c0 += BK) {
        size_t ga = (size_t)(m0 + lrow) * K + c0 + lseg;
        size_t gb = (size_t)browg * K + c0 + lseg;
        *(uint4*)&Ah[lrow][lseg] = *(const uint4*)(Aptr_hi + ga);
        *(uint4*)&Al[lrow][lseg] = *(const uint4*)(Aptr_lo + ga);
        *(uint4*)&Bh[lrow][lseg] = *(const uint4*)(Bptr_hi + gb);
        *(uint4*)&Bl[lrow][lseg] = *(const uint4*)(Bptr_lo + gb);
        __syncthreads();

        #pragma unroll
        for (int kk = 0; kk < 2; kk++) {
            const uint32_t koff = (uint32_t)(kk * 16 * 2);   // bytes
            uint32_t a_hi[2][4], a_lo[2][4];
            #pragma unroll
            for (int mt = 0; mt < 2; mt++) {
                ldm_x4(a_hi[mt][0], a_hi[mt][1], a_hi[mt][2], a_hi[mt][3],
                       aAddrBase[0] + mt * 16 * LDT * 2 + koff);
                ldm_x4(a_lo[mt][0], a_lo[mt][1], a_lo[mt][2], a_lo[mt][3],
                       aAddrBase[1] + mt * 16 * LDT * 2 + koff);
            }
            uint32_t b_hi[4], b_lo[4];
            ldm_x4(b_hi[0], b_hi[1], b_hi[2], b_hi[3], bAddrBase[0] + koff);
            ldm_x4(b_lo[0], b_lo[1], b_lo[2], b_lo[3], bAddrBase[1] + koff);

            #pragma unroll
            for (int mt = 0; mt < 2; mt++)
                #pragma unroll
                for (int nt = 0; nt < 2; nt++) {
                    mma_bf16(acc[mt][nt], a_hi[mt], b_hi[nt * 2], b_hi[nt * 2 + 1]);
                    mma_bf16(acc[mt][nt], a_hi[mt], b_lo[nt * 2], b_lo[nt * 2 + 1]);
                    mma_bf16(acc[mt][nt], a_lo[mt], b_hi[nt * 2], b_hi[nt * 2 + 1]);
                }
        }
        __syncthreads();
    }

    if constexpr (!IS_STEP) {
        // write g_xp + bias
        #pragma unroll
        for (int mt = 0; mt < 2; mt++) {
            int r = m0 + wm * 32 + mt * 16 + (lane >> 2);
            #pragma unroll
            for (int nt = 0; nt < 2; nt++) {
                int nn = wn * 16 + nt * 8 + (lane & 3) * 2;
                float b0v = sbias[nn], b1v = sbias[nn + 1];
                int n = n0 + nn;
                g_xp[(size_t)r * G4 + n]           = acc[mt][nt][0] + b0v;
                g_xp[(size_t)r * G4 + n + 1]       = acc[mt][nt][1] + b1v;
                g_xp[(size_t)(r + 8) * G4 + n]     = acc[mt][nt][2] + b0v;
                g_xp[(size_t)(r + 8) * G4 + n + 1] = acc[mt][nt][3] + b1v;
            }
        }
    } else {
        __shared__ float gst[BM][GST];
        #pragma unroll
        for (int mt = 0; mt < 2; mt++) {
            int r = wm * 32 + mt * 16 + (lane >> 2);
            #pragma unroll
            for (int nt = 0; nt < 2; nt++) {
                int cc = wn * 16 + nt * 8 + (lane & 3) * 2;
                gst[r][cc]         = acc[mt][nt][0];
                gst[r][cc + 1]     = acc[mt][nt][1];
                gst[r + 8][cc]     = acc[mt][nt][2];
                gst[r + 8][cc + 1] = acc[mt][nt][3];
            }
        }
        __syncthreads();

        __nv_bfloat16* hb_hi = layer ? g_h_hi1 : g_h_hi0;
        __nv_bfloat16* hb_lo = layer ? g_h_lo1 : g_h_lo0;
        __nv_bfloat16* ho_hi = hb_hi + (size_t)t * NB * H;
        __nv_bfloat16* ho_lo = hb_lo + (size_t)t * NB * H;
        float* cst = layer ? g_c1 : g_c0;
        const float* xp = g_xp + (size_t)t * NB * G4;
        const bool wbase = (layer == 1) && (t == T_STEPS - 1);

        #pragma unroll
        for (int i = 0; i < 4; i++) {
            int p  = tid + i * 256;
            int bb = p >> 4, jj = p & 15;
            int b  = m0 + bb;
            const float* xr = xp + (size_t)b * G4 + j0 + jj;
            float gi = gst[bb][jj]      + xr[0 * H];
            float gf = gst[bb][16 + jj] + xr[1 * H];
            float gg = gst[bb][32 + jj] + xr[2 * H];
            float go = gst[bb][48 + jj] + xr[3 * H];
            float iv = sigf(gi), fv = sigf(gf), gv = tanhf(gg), ov = sigf(go);
            size_t idx = (size_t)b * H + j0 + jj;
            float cn = fv * cst[idx] + iv * gv;
            cst[idx] = cn;
            float hv = ov * tanhf(cn);
            __nv_bfloat16 hh = __float2bfloat16(hv);
            ho_hi[idx] = hh;
            ho_lo[idx] = __float2bfloat16(hv - __bfloat162float(hh));
            if (wbase) g_base[idx] = hv;
        }
    }
}

// ---------------- heads ----------------
__global__ void heads_kernel(const float* __restrict__ cls_W, const float* __restrict__ cls_b,
                             const float* __restrict__ bbox_W, const float* __restrict__ bbox_b,
                             float* __restrict__ out) {
    __shared__ float base[H];
    int b = blockIdx.x;
    const float* src = g_base + (size_t)b * H;
    for (int k = threadIdx.x; k < H; k += blockDim.x) base[k] = src[k];
    __syncthreads();
    for (int o = threadIdx.x; o < 42; o += blockDim.x) {
        const float* w = (o < 40) ? &cls_W[o * H] : &bbox_W[(o - 40) * H];
        float s = (o < 40) ? cls_b[o] : bbox_b[o - 40];
        #pragma unroll 8
        for (int k = 0; k < H; k++) s += base[k] * w[k];
        if (o < 40) out[b * 40 + o] = s;
        else        out[NB * 40 + b * 2 + (o - 40)] = s;
    }
}

extern "C" void kernel_launch(void* const* d_in, const int* in_sizes, int n_in,
                              void* d_out, int out_size) {
    const float* proposals = (const float*)d_in[2];
    const float* Wih0 = (const float*)d_in[4];
    const float* Whh0 = (const float*)d_in[5];
    const float* bih0 = (const float*)d_in[6];
    const float* bhh0 = (const float*)d_in[7];
    const float* Wih1 = (const float*)d_in[8];
    const float* Whh1 = (const float*)d_in[9];
    const float* bih1 = (const float*)d_in[10];
    const float* bhh1 = (const float*)d_in[11];
    const float* cls_W  = (const float*)d_in[12];
    const float* cls_b  = (const float*)d_in[13];
    const float* bbox_W = (const float*)d_in[14];
    const float* bbox_b = (const float*)d_in[15];
    float* out = (float*)d_out;

    zero_kernel<<<256, 256>>>(out, out_size);

    conv_w<<<(G4 * CIN + 255) / 256, 256>>>(Wih0, 0, G4 * CIN);
    conv_w<<<(G4 * H + 255) / 256, 256>>>(Whh0, 1, G4 * H);
    conv_w<<<(G4 * H + 255) / 256, 256>>>(Wih1, 2, G4 * H);
    conv_w<<<(G4 * H + 255) / 256, 256>>>(Whh1, 3, G4 * H);
    conv_x<<<(T_STEPS * NB * CIN + 255) / 256, 256>>>(proposals);

    dim3 gx(G4 / BN, (T_STEPS * NB) / BM);   // (32, 800)
    dim3 gs(H / 16, NB / BM);                // (32, 4)

    gemm_mma<false><<<gx, 256>>>(CIN, 0, 0, bih0, bhh0);
    for (int t = 0; t < T_STEPS; t++)
        gemm_mma<true><<<gs, 256>>>(H, t, 0, nullptr, nullptr);

    gemm_mma<false><<<gx, 256>>>(H, 0, 1, bih1, bhh1);
    for (int t = 0; t < T_STEPS; t++)
        gemm_mma<true><<<gs, 256>>>(H, t, 1, nullptr, nullptr);

    heads_kernel<<<NB, 64>>>(cls_W, cls_b, bbox_W, bbox_b, out);
}